// round 1
// baseline (speedup 1.0000x reference)
#include <cuda_runtime.h>
#include <cstdint>

// ---------------------------------------------------------------------------
// NeuralCDE fused rollout via tf32 mma.sync GEMMs.
//   g  = x0 @ W_pe + b_pe                   [8192,256]
//   z0 = x0 @ W_hi + b_hi                   [8192,1024]
//   q  = g  @ W1[1024:,:]                   [8192,1024]   (step-invariant!)
//   50x: h = tanh(z @ W1[:1024,:] + t*q + b1)
//        z = z + dt*(h @ W2 + b2)
//   out = z @ W_ro + b_ro
// ---------------------------------------------------------------------------

static constexpr int BATCH = 8192;
static constexpr int DIN   = 1024;
static constexpr int PATHD = 256;
static constexpr int HID   = 1024;
static constexpr int NSTEP = 50;

// scratch (device globals: allocation-free per harness rules)
__device__ float g_buf [(size_t)BATCH * PATHD];
__device__ float q_buf [(size_t)BATCH * HID];
__device__ float z_bufg[(size_t)BATCH * HID];
__device__ float h_bufg[(size_t)BATCH * HID];
__device__ float zero_bias[1024];   // .bss -> zeros

// ---------------- GEMM tile configuration ----------------
static constexpr int BM = 128, BN = 128, BK = 32;
static constexpr int STAGES = 3, NTHREADS = 256;
static constexpr int ASTR = BK + 4;    // 36 floats  (conflict-free frag loads)
static constexpr int BSTR = BN + 4;    // 132 floats
static constexpr int ASZ  = BM * ASTR; // 4608
static constexpr int BSZ  = BK * BSTR; // 4224
static constexpr int SMEM_BYTES = STAGES * (ASZ + BSZ) * 4; // 105984 B

__device__ __forceinline__ uint32_t f2tf(float x) {
    uint32_t r;
    asm("cvt.rna.tf32.f32 %0, %1;" : "=r"(r) : "f"(x));
    return r;
}

// MODE 0: C = acc + bias
// MODE 1: C = tanh(acc + coef*extra + bias)          (h-step, extra=q, coef=t)
// MODE 2: C = extra + coef*(acc + bias)              (z-step, extra=z, coef=dt)
template<int MODE>
__global__ __launch_bounds__(NTHREADS, 1)
void gemm_tf32(const float* __restrict__ A, const float* __restrict__ Bw,
               float* __restrict__ C, int M, int N, int K,
               const float* __restrict__ bias, const float* __restrict__ extra,
               float coef)
{
    extern __shared__ float smem[];
    float* As = smem;
    float* Bs = smem + STAGES * ASZ;

    const int tid   = threadIdx.x;
    const int bm    = blockIdx.y, bn = blockIdx.x;
    const int wid   = tid >> 5, lane = tid & 31;
    const int gid   = lane >> 2, tig = lane & 3;     // quad group / thread-in-group
    const int warp_m = wid & 3, warp_n = wid >> 2;   // 4x2 warp grid -> 32x64 per warp

    const int KT = K / BK;

    auto load_tile = [&](int kt, int stage) {
        const float* Ag = A + (size_t)(bm * BM) * K + (size_t)kt * BK;
        float* Asb = As + stage * ASZ;
#pragma unroll
        for (int i = 0; i < 4; ++i) {
            int lin = i * NTHREADS + tid;
            int r = lin >> 3, kc = (lin & 7) << 2;
            uint32_t sa = (uint32_t)__cvta_generic_to_shared(Asb + r * ASTR + kc);
            const float* ga = Ag + (size_t)r * K + kc;
            asm volatile("cp.async.cg.shared.global [%0], [%1], 16;" :: "r"(sa), "l"(ga));
        }
        const float* Bg = Bw + (size_t)(kt * BK) * N + bn * BN;
        float* Bsb = Bs + stage * BSZ;
#pragma unroll
        for (int i = 0; i < 4; ++i) {
            int lin = i * NTHREADS + tid;
            int r = lin >> 5, nc = (lin & 31) << 2;
            uint32_t sa = (uint32_t)__cvta_generic_to_shared(Bsb + r * BSTR + nc);
            const float* ga = Bg + (size_t)r * N + nc;
            asm volatile("cp.async.cg.shared.global [%0], [%1], 16;" :: "r"(sa), "l"(ga));
        }
        asm volatile("cp.async.commit_group;");
    };

    float acc[2][8][4];
#pragma unroll
    for (int a = 0; a < 2; ++a)
#pragma unroll
        for (int b = 0; b < 8; ++b)
#pragma unroll
            for (int c = 0; c < 4; ++c) acc[a][b][c] = 0.f;

    for (int s = 0; s < STAGES - 1; ++s) load_tile(s, s);

    for (int kt = 0; kt < KT; ++kt) {
        if (kt < KT - (STAGES - 1))
            asm volatile("cp.async.wait_group %0;" :: "n"(STAGES - 2));
        else
            asm volatile("cp.async.wait_group 0;");
        __syncthreads();

        int pf = kt + STAGES - 1;
        if (pf < KT) load_tile(pf, pf % STAGES);

        const float* Asb = As + (kt % STAGES) * ASZ;
        const float* Bsb = Bs + (kt % STAGES) * BSZ;

#pragma unroll
        for (int ks = 0; ks < BK / 8; ++ks) {
            uint32_t af[2][4], bf[8][2];
#pragma unroll
            for (int mi = 0; mi < 2; ++mi) {
                int r0 = warp_m * 32 + mi * 16 + gid;
                af[mi][0] = f2tf(Asb[(size_t)(r0)     * ASTR + ks * 8 + tig]);
                af[mi][1] = f2tf(Asb[(size_t)(r0 + 8) * ASTR + ks * 8 + tig]);
                af[mi][2] = f2tf(Asb[(size_t)(r0)     * ASTR + ks * 8 + tig + 4]);
                af[mi][3] = f2tf(Asb[(size_t)(r0 + 8) * ASTR + ks * 8 + tig + 4]);
            }
#pragma unroll
            for (int ni = 0; ni < 8; ++ni) {
                int c0 = warp_n * 64 + ni * 8 + gid;
                bf[ni][0] = f2tf(Bsb[(size_t)(ks * 8 + tig)     * BSTR + c0]);
                bf[ni][1] = f2tf(Bsb[(size_t)(ks * 8 + tig + 4) * BSTR + c0]);
            }
#pragma unroll
            for (int mi = 0; mi < 2; ++mi)
#pragma unroll
                for (int ni = 0; ni < 8; ++ni) {
                    asm volatile(
                        "mma.sync.aligned.m16n8k8.row.col.f32.tf32.tf32.f32 "
                        "{%0,%1,%2,%3}, {%4,%5,%6,%7}, {%8,%9}, {%0,%1,%2,%3};"
                        : "+f"(acc[mi][ni][0]), "+f"(acc[mi][ni][1]),
                          "+f"(acc[mi][ni][2]), "+f"(acc[mi][ni][3])
                        : "r"(af[mi][0]), "r"(af[mi][1]), "r"(af[mi][2]), "r"(af[mi][3]),
                          "r"(bf[ni][0]), "r"(bf[ni][1]));
                }
        }
        __syncthreads();
    }

    // ---------------- epilogue ----------------
    const int rbase = bm * BM + warp_m * 32;
    const int cbase = bn * BN + warp_n * 64;
#pragma unroll
    for (int mi = 0; mi < 2; ++mi) {
#pragma unroll
        for (int h2 = 0; h2 < 2; ++h2) {
            int row = rbase + mi * 16 + h2 * 8 + gid;
#pragma unroll
            for (int ni = 0; ni < 8; ++ni) {
                int col = cbase + ni * 8 + tig * 2;
                float v0 = acc[mi][ni][h2 * 2 + 0];
                float v1 = acc[mi][ni][h2 * 2 + 1];
                float b0v = bias[col], b1v = bias[col + 1];
                size_t off = (size_t)row * N + col;
                if (MODE == 0) {
                    v0 += b0v; v1 += b1v;
                } else if (MODE == 1) {
                    float2 q2 = *reinterpret_cast<const float2*>(extra + off);
                    v0 = tanhf(v0 + coef * q2.x + b0v);
                    v1 = tanhf(v1 + coef * q2.y + b1v);
                } else {
                    float2 z2 = *reinterpret_cast<const float2*>(extra + off);
                    v0 = z2.x + coef * (v0 + b0v);
                    v1 = z2.y + coef * (v1 + b1v);
                }
                *reinterpret_cast<float2*>(C + off) = make_float2(v0, v1);
            }
        }
    }
}

template<int MODE>
static void run_gemm(const float* A, const float* Bw, float* C, int M, int N, int K,
                     const float* bias, const float* extra, float coef)
{
    cudaFuncSetAttribute(gemm_tf32<MODE>,
                         cudaFuncAttributeMaxDynamicSharedMemorySize, SMEM_BYTES);
    dim3 grid(N / BN, M / BM);
    gemm_tf32<MODE><<<grid, NTHREADS, SMEM_BYTES>>>(A, Bw, C, M, N, K, bias, extra, coef);
}

extern "C" void kernel_launch(void* const* d_in, const int* in_sizes, int n_in,
                              void* d_out, int out_size)
{
    const float* x0   = (const float*)d_in[0];
    const float* W_pe = (const float*)d_in[1];
    const float* b_pe = (const float*)d_in[2];
    const float* W_hi = (const float*)d_in[3];
    const float* b_hi = (const float*)d_in[4];
    const float* W1   = (const float*)d_in[5];   // [1280, 1024]
    const float* b1   = (const float*)d_in[6];
    const float* W2   = (const float*)d_in[7];
    const float* b2   = (const float*)d_in[8];
    const float* W_ro = (const float*)d_in[9];
    const float* b_ro = (const float*)d_in[10];
    float* out = (float*)d_out;

    float *g, *q, *z, *h, *zb;
    cudaGetSymbolAddress((void**)&g,  g_buf);
    cudaGetSymbolAddress((void**)&q,  q_buf);
    cudaGetSymbolAddress((void**)&z,  z_bufg);
    cudaGetSymbolAddress((void**)&h,  h_bufg);
    cudaGetSymbolAddress((void**)&zb, zero_bias);

    const float dt = 1.0f / (float)NSTEP;

    // prologue
    run_gemm<0>(x0, W_pe, g, BATCH, PATHD, DIN, b_pe, nullptr, 0.f);
    run_gemm<0>(x0, W_hi, z, BATCH, HID,   DIN, b_hi, nullptr, 0.f);
    run_gemm<0>(g, W1 + (size_t)HID * HID, q, BATCH, HID, PATHD, zb, nullptr, 0.f);

    // rollout: t_i = i*dt, i = 1..50
    for (int s = 1; s <= NSTEP; ++s) {
        run_gemm<1>(z, W1, h, BATCH, HID, HID, b1, q, dt * (float)s);
        run_gemm<2>(h, W2, z, BATCH, HID, HID, b2, z, dt);
    }

    // readout
    run_gemm<0>(z, W_ro, out, BATCH, HID, HID, b_ro, nullptr, 0.f);
}

// round 3
// speedup vs baseline: 1.2532x; 1.2532x over previous
#include <cuda_runtime.h>
#include <cstdint>

// ---------------------------------------------------------------------------
// NeuralCDE fused rollout, tf32 mma.sync, all operands pre-rounded to tf32
// (rna) in gmem so the GEMM inner loop has ZERO cvt instructions.
//   g  = rnd(x0r @ Wpe + b_pe)
//   q  = g @ W1b                       (step-invariant path term, fp32)
//   z0 = x0r @ Whi + b_hi              (z fp32 carried + zr rounded)
//   50x: h = rnd(tanh(zr @ W1a + t*q + b1))
//        z = z + dt*(h @ W2 + b2); zr = rnd(z)
//   out = zr @ Wro + b_ro
// ---------------------------------------------------------------------------

static constexpr int BATCH = 8192;
static constexpr int DIN   = 1024;
static constexpr int PATHD = 256;
static constexpr int HID   = 1024;
static constexpr int NSTEP = 50;

// ---------------- device scratch ----------------
__device__ float x0r_buf[(size_t)BATCH * DIN];
__device__ float g_buf  [(size_t)BATCH * PATHD];   // rounded
__device__ float q_buf  [(size_t)BATCH * HID];     // fp32
__device__ float z_buf  [(size_t)BATCH * HID];     // fp32 carried state
__device__ float zr_buf [(size_t)BATCH * HID];     // rounded copy of z
__device__ float h_buf  [(size_t)BATCH * HID];     // rounded
__device__ float Wpe_r [(size_t)DIN * PATHD];
__device__ float Whi_r [(size_t)DIN * HID];
__device__ float W1_r  [(size_t)(HID + PATHD) * HID];
__device__ float W2_r  [(size_t)HID * HID];
__device__ float Wro_r [(size_t)HID * HID];
__device__ float zero_bias[HID];                   // .bss zeros

// ---------------- GEMM tile configuration ----------------
static constexpr int BM = 128, BN = 256, BK = 32;
static constexpr int STAGES = 3, NTHREADS = 256;
static constexpr int ASTR = BK + 4;    // 36
static constexpr int BSTR = BN + 4;    // 260
static constexpr int ASZ  = BM * ASTR; // 4608 floats
static constexpr int BSZ  = BK * BSTR; // 8320 floats
static constexpr int SMEM_BYTES = STAGES * (ASZ + BSZ) * 4; // 155136 B

__device__ __forceinline__ float rnd_tf32(float x) {
    uint32_t r;
    asm("cvt.rna.tf32.f32 %0, %1;" : "=r"(r) : "f"(x));
    return __uint_as_float(r);
}

// MODE 0: C = acc + bias                                   (fp32 out)
// MODE 1: C = rnd(tanh(acc + coef*extra + bias))           (h-step)
// MODE 2: v = extra + coef*(acc + bias); C = v; Cr = rnd(v) (z-step)
// MODE 3: v = acc + bias;                C = v; Cr = rnd(v) (z0)
// MODE 4: C = rnd(acc + bias)                               (g)
template<int MODE>
__global__ __launch_bounds__(NTHREADS, 1)
void gemm_tf32(const float* __restrict__ A, const float* __restrict__ Bw,
               float* __restrict__ C, float* __restrict__ Cr,
               int N, int K,
               const float* __restrict__ bias, const float* __restrict__ extra,
               float coef)
{
    extern __shared__ float smem[];
    float* As = smem;
    float* Bs = smem + STAGES * ASZ;

    const int tid   = threadIdx.x;
    const int bm    = blockIdx.y, bn = blockIdx.x;
    const int wid   = tid >> 5, lane = tid & 31;
    const int gid   = lane >> 2, tig = lane & 3;
    const int warp_m = wid & 1, warp_n = wid >> 1;   // 2x4 warp grid, 64x64/warp

    const int KT = K / BK;

    auto load_tile = [&](int kt, int stage) {
        const float* Ag = A + (size_t)(bm * BM) * K + (size_t)kt * BK;
        float* Asb = As + stage * ASZ;
#pragma unroll
        for (int i = 0; i < 4; ++i) {
            int lin = i * NTHREADS + tid;
            int r = lin >> 3, kc = (lin & 7) << 2;
            uint32_t sa = (uint32_t)__cvta_generic_to_shared(Asb + r * ASTR + kc);
            const float* ga = Ag + (size_t)r * K + kc;
            asm volatile("cp.async.cg.shared.global [%0], [%1], 16;" :: "r"(sa), "l"(ga));
        }
        const float* Bg = Bw + (size_t)(kt * BK) * N + bn * BN;
        float* Bsb = Bs + stage * BSZ;
#pragma unroll
        for (int i = 0; i < 8; ++i) {
            int lin = i * NTHREADS + tid;
            int r = lin >> 6, nc = (lin & 63) << 2;
            uint32_t sa = (uint32_t)__cvta_generic_to_shared(Bsb + r * BSTR + nc);
            const float* ga = Bg + (size_t)r * N + nc;
            asm volatile("cp.async.cg.shared.global [%0], [%1], 16;" :: "r"(sa), "l"(ga));
        }
        asm volatile("cp.async.commit_group;");
    };

    float acc[4][8][4];
#pragma unroll
    for (int a = 0; a < 4; ++a)
#pragma unroll
        for (int b = 0; b < 8; ++b)
#pragma unroll
            for (int c = 0; c < 4; ++c) acc[a][b][c] = 0.f;

    for (int s = 0; s < STAGES - 1; ++s) load_tile(s, s);

    for (int kt = 0; kt < KT; ++kt) {
        if (kt < KT - (STAGES - 1))
            asm volatile("cp.async.wait_group %0;" :: "n"(STAGES - 2));
        else
            asm volatile("cp.async.wait_group 0;");
        __syncthreads();

        int pf = kt + STAGES - 1;
        if (pf < KT) load_tile(pf, pf % STAGES);

        const float* Asb = As + (kt % STAGES) * ASZ;
        const float* Bsb = Bs + (kt % STAGES) * BSZ;

#pragma unroll
        for (int ks = 0; ks < BK / 8; ++ks) {
            uint32_t af[4][4], bf[8][2];
#pragma unroll
            for (int mi = 0; mi < 4; ++mi) {
                int r0 = warp_m * 64 + mi * 16 + gid;
                af[mi][0] = __float_as_uint(Asb[(size_t)(r0)     * ASTR + ks * 8 + tig]);
                af[mi][1] = __float_as_uint(Asb[(size_t)(r0 + 8) * ASTR + ks * 8 + tig]);
                af[mi][2] = __float_as_uint(Asb[(size_t)(r0)     * ASTR + ks * 8 + tig + 4]);
                af[mi][3] = __float_as_uint(Asb[(size_t)(r0 + 8) * ASTR + ks * 8 + tig + 4]);
            }
#pragma unroll
            for (int ni = 0; ni < 8; ++ni) {
                int c0 = warp_n * 64 + ni * 8 + gid;
                bf[ni][0] = __float_as_uint(Bsb[(size_t)(ks * 8 + tig)     * BSTR + c0]);
                bf[ni][1] = __float_as_uint(Bsb[(size_t)(ks * 8 + tig + 4) * BSTR + c0]);
            }
#pragma unroll
            for (int mi = 0; mi < 4; ++mi)
#pragma unroll
                for (int ni = 0; ni < 8; ++ni) {
                    asm volatile(
                        "mma.sync.aligned.m16n8k8.row.col.f32.tf32.tf32.f32 "
                        "{%0,%1,%2,%3}, {%4,%5,%6,%7}, {%8,%9}, {%0,%1,%2,%3};"
                        : "+f"(acc[mi][ni][0]), "+f"(acc[mi][ni][1]),
                          "+f"(acc[mi][ni][2]), "+f"(acc[mi][ni][3])
                        : "r"(af[mi][0]), "r"(af[mi][1]), "r"(af[mi][2]), "r"(af[mi][3]),
                          "r"(bf[ni][0]), "r"(bf[ni][1]));
                }
        }
        __syncthreads();
    }

    // ---------------- epilogue ----------------
    const int rbase = bm * BM + warp_m * 64;
    const int cbase = bn * BN + warp_n * 64;
#pragma unroll
    for (int mi = 0; mi < 4; ++mi) {
#pragma unroll
        for (int h2 = 0; h2 < 2; ++h2) {
            int row = rbase + mi * 16 + h2 * 8 + gid;
#pragma unroll
            for (int ni = 0; ni < 8; ++ni) {
                int col = cbase + ni * 8 + tig * 2;
                float v0 = acc[mi][ni][h2 * 2 + 0];
                float v1 = acc[mi][ni][h2 * 2 + 1];
                float b0v = bias[col], b1v = bias[col + 1];
                size_t off = (size_t)row * N + col;
                v0 += b0v; v1 += b1v;
                if (MODE == 1) {
                    float2 e = *reinterpret_cast<const float2*>(extra + off);
                    v0 = rnd_tf32(tanhf(v0 + coef * e.x));
                    v1 = rnd_tf32(tanhf(v1 + coef * e.y));
                } else if (MODE == 2) {
                    float2 e = *reinterpret_cast<const float2*>(extra + off);
                    v0 = e.x + coef * v0;
                    v1 = e.y + coef * v1;
                } else if (MODE == 4) {
                    v0 = rnd_tf32(v0); v1 = rnd_tf32(v1);
                }
                *reinterpret_cast<float2*>(C + off) = make_float2(v0, v1);
                if (MODE == 2 || MODE == 3) {
                    *reinterpret_cast<float2*>(Cr + off) =
                        make_float2(rnd_tf32(v0), rnd_tf32(v1));
                }
            }
        }
    }
}

__global__ void round_copy(const float4* __restrict__ in, float4* __restrict__ out, int n4)
{
    int i = blockIdx.x * blockDim.x + threadIdx.x;
    if (i < n4) {
        float4 v = in[i];
        out[i] = make_float4(rnd_tf32(v.x), rnd_tf32(v.y), rnd_tf32(v.z), rnd_tf32(v.w));
    }
}

template<int MODE>
static void run_gemm(const float* A, const float* Bw, float* C, float* Cr,
                     int M, int N, int K,
                     const float* bias, const float* extra, float coef)
{
    cudaFuncSetAttribute(gemm_tf32<MODE>,
                         cudaFuncAttributeMaxDynamicSharedMemorySize, SMEM_BYTES);
    dim3 grid(N / BN, M / BM);
    gemm_tf32<MODE><<<grid, NTHREADS, SMEM_BYTES>>>(A, Bw, C, Cr, N, K, bias, extra, coef);
}

static void round_to(const float* src, float* dst, size_t n)
{
    int n4 = (int)(n / 4);
    round_copy<<<(n4 + 255) / 256, 256>>>((const float4*)src, (float4*)dst, n4);
}

extern "C" void kernel_launch(void* const* d_in, const int* in_sizes, int n_in,
                              void* d_out, int out_size)
{
    const float* x0   = (const float*)d_in[0];
    const float* W_pe = (const float*)d_in[1];
    const float* b_pe = (const float*)d_in[2];
    const float* W_hi = (const float*)d_in[3];
    const float* b_hi = (const float*)d_in[4];
    const float* W1   = (const float*)d_in[5];   // [1280, 1024]
    const float* b1   = (const float*)d_in[6];
    const float* W2   = (const float*)d_in[7];
    const float* b2   = (const float*)d_in[8];
    const float* W_ro = (const float*)d_in[9];
    const float* b_ro = (const float*)d_in[10];
    float* out = (float*)d_out;

    float *x0r, *g, *q, *z, *zr, *h, *wpe, *whi, *w1r, *w2r, *wro, *zb;
    cudaGetSymbolAddress((void**)&x0r, x0r_buf);
    cudaGetSymbolAddress((void**)&g,   g_buf);
    cudaGetSymbolAddress((void**)&q,   q_buf);
    cudaGetSymbolAddress((void**)&z,   z_buf);
    cudaGetSymbolAddress((void**)&zr,  zr_buf);
    cudaGetSymbolAddress((void**)&h,   h_buf);
    cudaGetSymbolAddress((void**)&wpe, Wpe_r);
    cudaGetSymbolAddress((void**)&whi, Whi_r);
    cudaGetSymbolAddress((void**)&w1r, W1_r);
    cudaGetSymbolAddress((void**)&w2r, W2_r);
    cudaGetSymbolAddress((void**)&wro, Wro_r);
    cudaGetSymbolAddress((void**)&zb,  zero_bias);

    const float dt = 1.0f / (float)NSTEP;

    // pre-round all GEMM operands (removes all cvt from GEMM inner loops)
    round_to(x0,   x0r, (size_t)BATCH * DIN);
    round_to(W_pe, wpe, (size_t)DIN * PATHD);
    round_to(W_hi, whi, (size_t)DIN * HID);
    round_to(W1,   w1r, (size_t)(HID + PATHD) * HID);
    round_to(W2,   w2r, (size_t)HID * HID);
    round_to(W_ro, wro, (size_t)HID * HID);

    const float* w1a = w1r;                         // [1024,1024]
    const float* w1b = w1r + (size_t)HID * HID;     // [256,1024]

    // prologue
    run_gemm<4>(x0r, wpe, g, nullptr, BATCH, PATHD, DIN, b_pe, nullptr, 0.f);
    run_gemm<0>(g,   w1b, q, nullptr, BATCH, HID, PATHD, zb, nullptr, 0.f);
    run_gemm<3>(x0r, whi, z, zr,      BATCH, HID, DIN,  b_hi, nullptr, 0.f);

    // rollout: t_i = i*dt
    for (int s = 1; s <= NSTEP; ++s) {
        run_gemm<1>(zr, w1a, h, nullptr, BATCH, HID, HID, b1, q, dt * (float)s);
        run_gemm<2>(h,  w2r, z, zr,      BATCH, HID, HID, b2, z, dt);
    }

    // readout
    run_gemm<0>(zr, wro, out, nullptr, BATCH, HID, HID, b_ro, nullptr, 0.f);
}

// round 4
// speedup vs baseline: 2.0763x; 1.6567x over previous
#include <cuda_runtime.h>
#include <cuda_fp16.h>
#include <cstdint>

// ---------------------------------------------------------------------------
// NeuralCDE fused rollout, fp16 mma.sync (m16n8k16, fp32 accum).
//   g  = h16(x0 @ Wpe + b_pe)
//   q  = g @ W1b                       (step-invariant path term, fp32)
//   z0 = x0 @ Whi + b_hi               (z fp32 carried + zrh fp16)
//   50x: h = h16(tanh(zrh @ W1a + t*q + b1))
//        z = z + dt*(h @ W2 + b2); zrh = h16(z)
//   out = zrh @ Wro + b_ro
// Weights pre-transposed to [N,K] fp16; activations stored fp16.
// ---------------------------------------------------------------------------

static constexpr int BATCH = 8192;
static constexpr int DIN   = 1024;
static constexpr int PATHD = 256;
static constexpr int HID   = 1024;
static constexpr int NSTEP = 50;

// ---------------- device scratch ----------------
__device__ __half x0h_buf[(size_t)BATCH * DIN];
__device__ __half gh_buf [(size_t)BATCH * PATHD];
__device__ __half hh_buf [(size_t)BATCH * HID];
__device__ __half zrh_buf[(size_t)BATCH * HID];
__device__ float  q_buf  [(size_t)BATCH * HID];
__device__ float  z_buf  [(size_t)BATCH * HID];
__device__ __half WpeT  [(size_t)PATHD * DIN];
__device__ __half WhiT  [(size_t)HID * DIN];
__device__ __half W1aT  [(size_t)HID * HID];
__device__ __half W1bT  [(size_t)HID * PATHD];
__device__ __half W2T   [(size_t)HID * HID];
__device__ __half WroT  [(size_t)HID * HID];
__device__ float  zero_bias[HID];                  // .bss zeros

// ---------------- GEMM tile configuration ----------------
static constexpr int BM = 128, BN = 256, BK = 32;   // BK in halves (64B rows)
static constexpr int STAGES = 3, NTHREADS = 256;
static constexpr int ASTR = BK + 8;    // 40 halves (80B row stride)
static constexpr int BSTR = BK + 8;    // 40 halves
static constexpr int ASZ  = BM * ASTR; // 5120 halves
static constexpr int BSZ  = BN * BSTR; // 10240 halves
static constexpr int SMEM_BYTES = STAGES * (ASZ + BSZ) * 2; // 92160 B

// MODE 0: Cf = acc + bias                                     (q, out)
// MODE 1: Ch = h16(tanh(acc + coef*extra + bias))             (h-step)
// MODE 2: v = extra + coef*(acc + bias); Cf = v; Crh = h16(v) (z-step)
// MODE 3: v = acc + bias;               Cf = v; Crh = h16(v)  (z0)
// MODE 4: Ch = h16(acc + bias)                                (g)
template<int MODE>
__global__ __launch_bounds__(NTHREADS, 1)
void gemm_f16(const __half* __restrict__ A, const __half* __restrict__ Bw,
              float* __restrict__ Cf, __half* __restrict__ Ch,
              __half* __restrict__ Crh,
              int N, int K,
              const float* __restrict__ bias, const float* __restrict__ extra,
              float coef)
{
    extern __shared__ __half smem[];
    __half* As = smem;
    __half* Bs = smem + STAGES * ASZ;

    const int tid   = threadIdx.x;
    const int bm    = blockIdx.y, bn = blockIdx.x;
    const int wid   = tid >> 5, lane = tid & 31;
    const int gid   = lane >> 2, tig = lane & 3;
    const int warp_m = wid & 1, warp_n = wid >> 1;   // 2x4 warps, 64x64 per warp

    const int KT = K / BK;

    auto load_tile = [&](int kt, int stage) {
        // A tile: [BM][BK] halves, 4 x 16B chunks per row
        const __half* Ag = A + (size_t)(bm * BM) * K + (size_t)kt * BK;
        __half* Asb = As + stage * ASZ;
#pragma unroll
        for (int i = 0; i < 2; ++i) {
            int lin = i * NTHREADS + tid;
            int r = lin >> 2, c = (lin & 3) << 3;
            uint32_t sa = (uint32_t)__cvta_generic_to_shared(Asb + r * ASTR + c);
            const __half* ga = Ag + (size_t)r * K + c;
            asm volatile("cp.async.cg.shared.global [%0], [%1], 16;" :: "r"(sa), "l"(ga));
        }
        // B tile: [BN][BK] halves
        const __half* Bg = Bw + (size_t)(bn * BN) * K + (size_t)kt * BK;
        __half* Bsb = Bs + stage * BSZ;
#pragma unroll
        for (int i = 0; i < 4; ++i) {
            int lin = i * NTHREADS + tid;
            int r = lin >> 2, c = (lin & 3) << 3;
            uint32_t sa = (uint32_t)__cvta_generic_to_shared(Bsb + r * BSTR + c);
            const __half* ga = Bg + (size_t)r * K + c;
            asm volatile("cp.async.cg.shared.global [%0], [%1], 16;" :: "r"(sa), "l"(ga));
        }
        asm volatile("cp.async.commit_group;");
    };

    float acc[4][8][4];
#pragma unroll
    for (int a = 0; a < 4; ++a)
#pragma unroll
        for (int b = 0; b < 8; ++b)
#pragma unroll
            for (int c = 0; c < 4; ++c) acc[a][b][c] = 0.f;

    for (int s = 0; s < STAGES - 1; ++s) load_tile(s, s);

    for (int kt = 0; kt < KT; ++kt) {
        if (kt < KT - (STAGES - 1))
            asm volatile("cp.async.wait_group %0;" :: "n"(STAGES - 2));
        else
            asm volatile("cp.async.wait_group 0;");
        __syncthreads();

        int pf = kt + STAGES - 1;
        if (pf < KT) load_tile(pf, pf % STAGES);

        const __half* Asb = As + (kt % STAGES) * ASZ;
        const __half* Bsb = Bs + (kt % STAGES) * BSZ;

#pragma unroll
        for (int ks = 0; ks < BK / 16; ++ks) {
            uint32_t af[4][4], bf[8][2];
#pragma unroll
            for (int mi = 0; mi < 4; ++mi) {
                int r0 = warp_m * 64 + mi * 16 + gid;
                const __half* base = Asb + (size_t)r0 * ASTR + ks * 16 + tig * 2;
                af[mi][0] = *reinterpret_cast<const uint32_t*>(base);
                af[mi][1] = *reinterpret_cast<const uint32_t*>(base + 8 * ASTR);
                af[mi][2] = *reinterpret_cast<const uint32_t*>(base + 8);
                af[mi][3] = *reinterpret_cast<const uint32_t*>(base + 8 * ASTR + 8);
            }
#pragma unroll
            for (int ni = 0; ni < 8; ++ni) {
                int n0 = warp_n * 64 + ni * 8 + gid;
                const __half* base = Bsb + (size_t)n0 * BSTR + ks * 16 + tig * 2;
                bf[ni][0] = *reinterpret_cast<const uint32_t*>(base);
                bf[ni][1] = *reinterpret_cast<const uint32_t*>(base + 8);
            }
#pragma unroll
            for (int mi = 0; mi < 4; ++mi)
#pragma unroll
                for (int ni = 0; ni < 8; ++ni) {
                    asm volatile(
                        "mma.sync.aligned.m16n8k16.row.col.f32.f16.f16.f32 "
                        "{%0,%1,%2,%3}, {%4,%5,%6,%7}, {%8,%9}, {%0,%1,%2,%3};"
                        : "+f"(acc[mi][ni][0]), "+f"(acc[mi][ni][1]),
                          "+f"(acc[mi][ni][2]), "+f"(acc[mi][ni][3])
                        : "r"(af[mi][0]), "r"(af[mi][1]), "r"(af[mi][2]), "r"(af[mi][3]),
                          "r"(bf[ni][0]), "r"(bf[ni][1]));
                }
        }
        __syncthreads();
    }

    // ---------------- epilogue ----------------
    const int rbase = bm * BM + warp_m * 64;
    const int cbase = bn * BN + warp_n * 64;
#pragma unroll
    for (int mi = 0; mi < 4; ++mi) {
#pragma unroll
        for (int h2 = 0; h2 < 2; ++h2) {
            int row = rbase + mi * 16 + h2 * 8 + gid;
#pragma unroll
            for (int ni = 0; ni < 8; ++ni) {
                int col = cbase + ni * 8 + tig * 2;
                float v0 = acc[mi][ni][h2 * 2 + 0] + bias[col];
                float v1 = acc[mi][ni][h2 * 2 + 1] + bias[col + 1];
                size_t off = (size_t)row * N + col;
                if (MODE == 1) {
                    float2 e = *reinterpret_cast<const float2*>(extra + off);
                    v0 = tanhf(v0 + coef * e.x);
                    v1 = tanhf(v1 + coef * e.y);
                    *reinterpret_cast<__half2*>(Ch + off) =
                        __floats2half2_rn(v0, v1);
                } else if (MODE == 2) {
                    float2 e = *reinterpret_cast<const float2*>(extra + off);
                    v0 = e.x + coef * v0;
                    v1 = e.y + coef * v1;
                    *reinterpret_cast<float2*>(Cf + off) = make_float2(v0, v1);
                    *reinterpret_cast<__half2*>(Crh + off) =
                        __floats2half2_rn(v0, v1);
                } else if (MODE == 3) {
                    *reinterpret_cast<float2*>(Cf + off) = make_float2(v0, v1);
                    *reinterpret_cast<__half2*>(Crh + off) =
                        __floats2half2_rn(v0, v1);
                } else if (MODE == 4) {
                    *reinterpret_cast<__half2*>(Ch + off) =
                        __floats2half2_rn(v0, v1);
                } else {
                    *reinterpret_cast<float2*>(Cf + off) = make_float2(v0, v1);
                }
            }
        }
    }
}

// ---------------------------------------------------------------------------
// prep kernels
// ---------------------------------------------------------------------------
__global__ void transpose_h16(const float* __restrict__ in, __half* __restrict__ out,
                              int K, int N)   // in [K,N] fp32 -> out [N,K] fp16
{
    __shared__ float t[32][33];
    const int k0 = blockIdx.y * 32, n0 = blockIdx.x * 32;
    const int x = threadIdx.x, y = threadIdx.y;
#pragma unroll
    for (int i = 0; i < 32; i += 8)
        t[y + i][x] = in[(size_t)(k0 + y + i) * N + n0 + x];
    __syncthreads();
#pragma unroll
    for (int i = 0; i < 32; i += 8)
        out[(size_t)(n0 + y + i) * K + k0 + x] = __float2half_rn(t[x][y + i]);
}

__global__ void to_h16(const float4* __restrict__ in, __half2* __restrict__ out, int n4)
{
    int i = blockIdx.x * blockDim.x + threadIdx.x;
    if (i < n4) {
        float4 v = in[i];
        out[i * 2 + 0] = __floats2half2_rn(v.x, v.y);
        out[i * 2 + 1] = __floats2half2_rn(v.z, v.w);
    }
}

template<int MODE>
static void run_gemm(const __half* A, const __half* Bw,
                     float* Cf, __half* Ch, __half* Crh,
                     int M, int N, int K,
                     const float* bias, const float* extra, float coef)
{
    cudaFuncSetAttribute(gemm_f16<MODE>,
                         cudaFuncAttributeMaxDynamicSharedMemorySize, SMEM_BYTES);
    dim3 grid(N / BN, M / BM);
    gemm_f16<MODE><<<grid, NTHREADS, SMEM_BYTES>>>(A, Bw, Cf, Ch, Crh, N, K,
                                                   bias, extra, coef);
}

extern "C" void kernel_launch(void* const* d_in, const int* in_sizes, int n_in,
                              void* d_out, int out_size)
{
    const float* x0   = (const float*)d_in[0];
    const float* W_pe = (const float*)d_in[1];
    const float* b_pe = (const float*)d_in[2];
    const float* W_hi = (const float*)d_in[3];
    const float* b_hi = (const float*)d_in[4];
    const float* W1   = (const float*)d_in[5];   // [1280, 1024]
    const float* b1   = (const float*)d_in[6];
    const float* W2   = (const float*)d_in[7];
    const float* b2   = (const float*)d_in[8];
    const float* W_ro = (const float*)d_in[9];
    const float* b_ro = (const float*)d_in[10];
    float* out = (float*)d_out;

    __half *x0h, *gh, *hh, *zrh, *wpe, *whi, *w1a, *w1b, *w2, *wro;
    float *q, *z, *zb;
    cudaGetSymbolAddress((void**)&x0h, x0h_buf);
    cudaGetSymbolAddress((void**)&gh,  gh_buf);
    cudaGetSymbolAddress((void**)&hh,  hh_buf);
    cudaGetSymbolAddress((void**)&zrh, zrh_buf);
    cudaGetSymbolAddress((void**)&q,   q_buf);
    cudaGetSymbolAddress((void**)&z,   z_buf);
    cudaGetSymbolAddress((void**)&wpe, WpeT);
    cudaGetSymbolAddress((void**)&whi, WhiT);
    cudaGetSymbolAddress((void**)&w1a, W1aT);
    cudaGetSymbolAddress((void**)&w1b, W1bT);
    cudaGetSymbolAddress((void**)&w2,  W2T);
    cudaGetSymbolAddress((void**)&wro, WroT);
    cudaGetSymbolAddress((void**)&zb,  zero_bias);

    const float dt = 1.0f / (float)NSTEP;
    dim3 tb32(32, 8);

    // weight transposes [K,N] fp32 -> [N,K] fp16
    transpose_h16<<<dim3(PATHD/32, DIN/32), tb32>>>(W_pe, wpe, DIN, PATHD);
    transpose_h16<<<dim3(HID/32,   DIN/32), tb32>>>(W_hi, whi, DIN, HID);
    transpose_h16<<<dim3(HID/32,   HID/32), tb32>>>(W1,   w1a, HID, HID);
    transpose_h16<<<dim3(HID/32,   PATHD/32), tb32>>>(W1 + (size_t)HID * HID, w1b, PATHD, HID);
    transpose_h16<<<dim3(HID/32,   HID/32), tb32>>>(W2,   w2,  HID, HID);
    transpose_h16<<<dim3(HID/32,   HID/32), tb32>>>(W_ro, wro, HID, HID);

    int n4 = (BATCH * DIN) / 4;
    to_h16<<<(n4 + 255) / 256, 256>>>((const float4*)x0, (__half2*)x0h, n4);

    // prologue
    run_gemm<4>(x0h, wpe, nullptr, gh, nullptr, BATCH, PATHD, DIN, b_pe, nullptr, 0.f);
    run_gemm<0>(gh,  w1b, q, nullptr, nullptr,  BATCH, HID, PATHD, zb, nullptr, 0.f);
    run_gemm<3>(x0h, whi, z, nullptr, zrh,      BATCH, HID, DIN,  b_hi, nullptr, 0.f);

    // rollout: t_i = i*dt
    for (int s = 1; s <= NSTEP; ++s) {
        run_gemm<1>(zrh, w1a, nullptr, hh, nullptr, BATCH, HID, HID, b1, q, dt * (float)s);
        run_gemm<2>(hh,  w2,  z, nullptr, zrh,      BATCH, HID, HID, b2, z, dt);
    }

    // readout
    run_gemm<0>(zrh, wro, out, nullptr, nullptr, BATCH, HID, HID, b_ro, nullptr, 0.f);
}

// round 5
// speedup vs baseline: 2.3963x; 1.1541x over previous
#include <cuda_runtime.h>
#include <cuda_fp16.h>
#include <cstdint>

// ---------------------------------------------------------------------------
// NeuralCDE fused rollout, fp16 mma.sync m16n8k16 + ldmatrix, occ-2 tiles.
//   g  = h16(x0 @ Wpe + b_pe)
//   q  = h16(g @ W1b)                  (step-invariant path term)
//   z0 = x0 @ Whi + b_hi               (z fp32 carried + zrh fp16)
//   50x: h = h16(tanh(zrh @ W1a + t*q + b1))
//        z = z + dt*(h @ W2 + b2); zrh = h16(z)
//   out = zrh @ Wro + b_ro
// Weights pre-transposed to [N,K] fp16; activations fp16.
// ---------------------------------------------------------------------------

static constexpr int BATCH = 8192;
static constexpr int DIN   = 1024;
static constexpr int PATHD = 256;
static constexpr int HID   = 1024;
static constexpr int NSTEP = 50;

// ---------------- device scratch ----------------
__device__ __half x0h_buf[(size_t)BATCH * DIN];
__device__ __half gh_buf [(size_t)BATCH * PATHD];
__device__ __half hh_buf [(size_t)BATCH * HID];
__device__ __half zrh_buf[(size_t)BATCH * HID];
__device__ __half qh_buf [(size_t)BATCH * HID];
__device__ float  z_buf  [(size_t)BATCH * HID];
__device__ __half WpeT  [(size_t)PATHD * DIN];
__device__ __half WhiT  [(size_t)HID * DIN];
__device__ __half W1aT  [(size_t)HID * HID];
__device__ __half W1bT  [(size_t)HID * PATHD];
__device__ __half W2T   [(size_t)HID * HID];
__device__ __half WroT  [(size_t)HID * HID];
__device__ float  zero_bias[HID];                  // .bss zeros

// ---------------- GEMM tile configuration ----------------
static constexpr int BM = 128, BN = 128, BK = 32;   // BK halves (64B rows)
static constexpr int STAGES = 4, NTHREADS = 256;
static constexpr int STR  = BK + 8;    // 40 halves = 80B row stride
static constexpr int ASZ  = BM * STR;  // 5120 halves
static constexpr int BSZ  = BN * STR;  // 5120 halves
static constexpr int SMEM_BYTES = STAGES * (ASZ + BSZ) * 2; // 81920 B

__device__ __forceinline__ void ldmx4(uint32_t& r0, uint32_t& r1,
                                      uint32_t& r2, uint32_t& r3, uint32_t a) {
    asm volatile("ldmatrix.sync.aligned.m8n8.x4.shared.b16 {%0,%1,%2,%3}, [%4];"
                 : "=r"(r0), "=r"(r1), "=r"(r2), "=r"(r3) : "r"(a));
}

// MODE 0: Cf = acc + bias                                      (out)
// MODE 1: Ch = h16(tanh(acc + coef*extraH + bias))             (h-step)
// MODE 2: v = extraF + coef*(acc + bias); Cf = v; Crh = h16(v) (z-step)
// MODE 3: v = acc + bias;                Cf = v; Crh = h16(v)  (z0)
// MODE 4: Ch = h16(acc + bias)                                 (g, q)
template<int MODE>
__global__ __launch_bounds__(NTHREADS, 2)
void gemm_f16(const __half* __restrict__ A, const __half* __restrict__ Bw,
              float* __restrict__ Cf, __half* __restrict__ Ch,
              __half* __restrict__ Crh,
              int N, int K,
              const float* __restrict__ bias,
              const float* __restrict__ extraF,
              const __half* __restrict__ extraH,
              float coef)
{
    extern __shared__ __half smem[];
    __half* As = smem;
    __half* Bs = smem + STAGES * ASZ;

    const int tid   = threadIdx.x;
    const int bm    = blockIdx.y, bn = blockIdx.x;
    const int wid   = tid >> 5, lane = tid & 31;
    const int gid   = lane >> 2, tig = lane & 3;
    const int warp_m = wid & 1, warp_n = wid >> 1;   // 2x4 warps -> 64x32 per warp

    const int KT = K / BK;

    auto load_tile = [&](int kt, int stage) {
        const __half* Ag = A + (size_t)(bm * BM) * K + (size_t)kt * BK;
        __half* Asb = As + stage * ASZ;
#pragma unroll
        for (int i = 0; i < 2; ++i) {
            int lin = i * NTHREADS + tid;
            int r = lin >> 2, c = (lin & 3) << 3;
            uint32_t sa = (uint32_t)__cvta_generic_to_shared(Asb + r * STR + c);
            asm volatile("cp.async.cg.shared.global [%0], [%1], 16;"
                         :: "r"(sa), "l"(Ag + (size_t)r * K + c));
        }
        const __half* Bg = Bw + (size_t)(bn * BN) * K + (size_t)kt * BK;
        __half* Bsb = Bs + stage * BSZ;
#pragma unroll
        for (int i = 0; i < 2; ++i) {
            int lin = i * NTHREADS + tid;
            int r = lin >> 2, c = (lin & 3) << 3;
            uint32_t sa = (uint32_t)__cvta_generic_to_shared(Bsb + r * STR + c);
            asm volatile("cp.async.cg.shared.global [%0], [%1], 16;"
                         :: "r"(sa), "l"(Bg + (size_t)r * K + c));
        }
        asm volatile("cp.async.commit_group;");
    };

    float acc[4][4][4];
#pragma unroll
    for (int a = 0; a < 4; ++a)
#pragma unroll
        for (int b = 0; b < 4; ++b)
#pragma unroll
            for (int c = 0; c < 4; ++c) acc[a][b][c] = 0.f;

    // ldmatrix lane address components (in halves)
    const int a_row  = warp_m * 64 + (lane & 15);       // + mi*16
    const int a_koff = (lane >> 4) << 3;
    const int b_row  = warp_n * 32 + (lane & 7) + ((lane >> 4) << 3);  // + ni*16
    const int b_koff = ((lane >> 3) & 1) << 3;

    for (int s = 0; s < STAGES - 1; ++s) load_tile(s, s);

    for (int kt = 0; kt < KT; ++kt) {
        if (kt < KT - (STAGES - 1))
            asm volatile("cp.async.wait_group %0;" :: "n"(STAGES - 2));
        else
            asm volatile("cp.async.wait_group 0;");
        __syncthreads();

        int pf = kt + STAGES - 1;
        if (pf < KT) load_tile(pf, pf % STAGES);

        const __half* Asb = As + (kt % STAGES) * ASZ;
        const __half* Bsb = Bs + (kt % STAGES) * BSZ;

        const uint32_t a_base = (uint32_t)__cvta_generic_to_shared(
            Asb + (size_t)a_row * STR + a_koff);
        const uint32_t b_base = (uint32_t)__cvta_generic_to_shared(
            Bsb + (size_t)b_row * STR + b_koff);

#pragma unroll
        for (int ks = 0; ks < BK / 16; ++ks) {
            uint32_t af[4][4], bf[4][2];
#pragma unroll
            for (int mi = 0; mi < 4; ++mi)
                ldmx4(af[mi][0], af[mi][1], af[mi][2], af[mi][3],
                      a_base + (mi * 16 * STR + ks * 16) * 2);
#pragma unroll
            for (int np = 0; np < 2; ++np)
                ldmx4(bf[np*2][0], bf[np*2][1], bf[np*2+1][0], bf[np*2+1][1],
                      b_base + (np * 16 * STR + ks * 16) * 2);
#pragma unroll
            for (int mi = 0; mi < 4; ++mi)
#pragma unroll
                for (int ni = 0; ni < 4; ++ni) {
                    asm volatile(
                        "mma.sync.aligned.m16n8k16.row.col.f32.f16.f16.f32 "
                        "{%0,%1,%2,%3}, {%4,%5,%6,%7}, {%8,%9}, {%0,%1,%2,%3};"
                        : "+f"(acc[mi][ni][0]), "+f"(acc[mi][ni][1]),
                          "+f"(acc[mi][ni][2]), "+f"(acc[mi][ni][3])
                        : "r"(af[mi][0]), "r"(af[mi][1]), "r"(af[mi][2]), "r"(af[mi][3]),
                          "r"(bf[ni][0]), "r"(bf[ni][1]));
                }
        }
        __syncthreads();
    }

    // ---------------- epilogue ----------------
    const int rbase = bm * BM + warp_m * 64;
    const int cbase = bn * BN + warp_n * 32;
#pragma unroll
    for (int mi = 0; mi < 4; ++mi) {
#pragma unroll
        for (int h2 = 0; h2 < 2; ++h2) {
            int row = rbase + mi * 16 + h2 * 8 + gid;
#pragma unroll
            for (int ni = 0; ni < 4; ++ni) {
                int col = cbase + ni * 8 + tig * 2;
                float v0 = acc[mi][ni][h2 * 2 + 0] + bias[col];
                float v1 = acc[mi][ni][h2 * 2 + 1] + bias[col + 1];
                size_t off = (size_t)row * N + col;
                if (MODE == 1) {
                    float2 e = __half22float2(
                        *reinterpret_cast<const __half2*>(extraH + off));
                    v0 = tanhf(v0 + coef * e.x);
                    v1 = tanhf(v1 + coef * e.y);
                    *reinterpret_cast<__half2*>(Ch + off) = __floats2half2_rn(v0, v1);
                } else if (MODE == 2) {
                    float2 e = *reinterpret_cast<const float2*>(extraF + off);
                    v0 = e.x + coef * v0;
                    v1 = e.y + coef * v1;
                    *reinterpret_cast<float2*>(Cf + off) = make_float2(v0, v1);
                    *reinterpret_cast<__half2*>(Crh + off) = __floats2half2_rn(v0, v1);
                } else if (MODE == 3) {
                    *reinterpret_cast<float2*>(Cf + off) = make_float2(v0, v1);
                    *reinterpret_cast<__half2*>(Crh + off) = __floats2half2_rn(v0, v1);
                } else if (MODE == 4) {
                    *reinterpret_cast<__half2*>(Ch + off) = __floats2half2_rn(v0, v1);
                } else {
                    *reinterpret_cast<float2*>(Cf + off) = make_float2(v0, v1);
                }
            }
        }
    }
}

// ---------------------------------------------------------------------------
// prep kernels
// ---------------------------------------------------------------------------
__global__ void transpose_h16(const float* __restrict__ in, __half* __restrict__ out,
                              int K, int N)   // [K,N] fp32 -> [N,K] fp16
{
    __shared__ float t[32][33];
    const int k0 = blockIdx.y * 32, n0 = blockIdx.x * 32;
    const int x = threadIdx.x, y = threadIdx.y;
#pragma unroll
    for (int i = 0; i < 32; i += 8)
        t[y + i][x] = in[(size_t)(k0 + y + i) * N + n0 + x];
    __syncthreads();
#pragma unroll
    for (int i = 0; i < 32; i += 8)
        out[(size_t)(n0 + y + i) * K + k0 + x] = __float2half_rn(t[x][y + i]);
}

__global__ void to_h16(const float4* __restrict__ in, __half2* __restrict__ out, int n4)
{
    int i = blockIdx.x * blockDim.x + threadIdx.x;
    if (i < n4) {
        float4 v = in[i];
        out[i * 2 + 0] = __floats2half2_rn(v.x, v.y);
        out[i * 2 + 1] = __floats2half2_rn(v.z, v.w);
    }
}

template<int MODE>
static void run_gemm(const __half* A, const __half* Bw,
                     float* Cf, __half* Ch, __half* Crh,
                     int M, int N, int K,
                     const float* bias, const float* extraF,
                     const __half* extraH, float coef)
{
    cudaFuncSetAttribute(gemm_f16<MODE>,
                         cudaFuncAttributeMaxDynamicSharedMemorySize, SMEM_BYTES);
    dim3 grid(N / BN, M / BM);
    gemm_f16<MODE><<<grid, NTHREADS, SMEM_BYTES>>>(A, Bw, Cf, Ch, Crh, N, K,
                                                   bias, extraF, extraH, coef);
}

extern "C" void kernel_launch(void* const* d_in, const int* in_sizes, int n_in,
                              void* d_out, int out_size)
{
    const float* x0   = (const float*)d_in[0];
    const float* W_pe = (const float*)d_in[1];
    const float* b_pe = (const float*)d_in[2];
    const float* W_hi = (const float*)d_in[3];
    const float* b_hi = (const float*)d_in[4];
    const float* W1   = (const float*)d_in[5];   // [1280, 1024]
    const float* b1   = (const float*)d_in[6];
    const float* W2   = (const float*)d_in[7];
    const float* b2   = (const float*)d_in[8];
    const float* W_ro = (const float*)d_in[9];
    const float* b_ro = (const float*)d_in[10];
    float* out = (float*)d_out;

    __half *x0h, *gh, *hh, *zrh, *qh, *wpe, *whi, *w1a, *w1b, *w2, *wro;
    float *z, *zb;
    cudaGetSymbolAddress((void**)&x0h, x0h_buf);
    cudaGetSymbolAddress((void**)&gh,  gh_buf);
    cudaGetSymbolAddress((void**)&hh,  hh_buf);
    cudaGetSymbolAddress((void**)&zrh, zrh_buf);
    cudaGetSymbolAddress((void**)&qh,  qh_buf);
    cudaGetSymbolAddress((void**)&z,   z_buf);
    cudaGetSymbolAddress((void**)&wpe, WpeT);
    cudaGetSymbolAddress((void**)&whi, WhiT);
    cudaGetSymbolAddress((void**)&w1a, W1aT);
    cudaGetSymbolAddress((void**)&w1b, W1bT);
    cudaGetSymbolAddress((void**)&w2,  W2T);
    cudaGetSymbolAddress((void**)&wro, WroT);
    cudaGetSymbolAddress((void**)&zb,  zero_bias);

    const float dt = 1.0f / (float)NSTEP;
    dim3 tb32(32, 8);

    transpose_h16<<<dim3(PATHD/32, DIN/32), tb32>>>(W_pe, wpe, DIN, PATHD);
    transpose_h16<<<dim3(HID/32,   DIN/32), tb32>>>(W_hi, whi, DIN, HID);
    transpose_h16<<<dim3(HID/32,   HID/32), tb32>>>(W1,   w1a, HID, HID);
    transpose_h16<<<dim3(HID/32,   PATHD/32), tb32>>>(W1 + (size_t)HID * HID, w1b, PATHD, HID);
    transpose_h16<<<dim3(HID/32,   HID/32), tb32>>>(W2,   w2,  HID, HID);
    transpose_h16<<<dim3(HID/32,   HID/32), tb32>>>(W_ro, wro, HID, HID);

    int n4 = (BATCH * DIN) / 4;
    to_h16<<<(n4 + 255) / 256, 256>>>((const float4*)x0, (__half2*)x0h, n4);

    // prologue
    run_gemm<4>(x0h, wpe, nullptr, gh, nullptr, BATCH, PATHD, DIN, b_pe, nullptr, nullptr, 0.f);
    run_gemm<4>(gh,  w1b, nullptr, qh, nullptr, BATCH, HID, PATHD, zb, nullptr, nullptr, 0.f);
    run_gemm<3>(x0h, whi, z, nullptr, zrh,      BATCH, HID, DIN,  b_hi, nullptr, nullptr, 0.f);

    // rollout: t_i = i*dt
    for (int s = 1; s <= NSTEP; ++s) {
        run_gemm<1>(zrh, w1a, nullptr, hh, nullptr, BATCH, HID, HID, b1, nullptr, qh, dt * (float)s);
        run_gemm<2>(hh,  w2,  z, nullptr, zrh,      BATCH, HID, HID, b2, z, nullptr, dt);
    }

    // readout
    run_gemm<0>(zrh, wro, out, nullptr, nullptr, BATCH, HID, HID, b_ro, nullptr, nullptr, 0.f);
}

// round 6
// speedup vs baseline: 2.6465x; 1.1044x over previous
#include <cuda_runtime.h>
#include <cuda_fp16.h>
#include <cstdint>

// ---------------------------------------------------------------------------
// NeuralCDE rollout: persistent dependency-tracked fp16 mma.sync pipeline.
//   g  = h16(x0 @ Wpe + b_pe)
//   q  = h16(g @ W1b)                  (step-invariant path term)
//   z0 = x0 @ Whi + b_hi               (z fp32 carried + zrh fp16)
//   persistent kernel, 100 chained GEMMs (tile-level dependencies):
//     h = h16(tanh.approx(zrh @ W1a + t*q + b1))
//     z = z + dt*(h @ W2 + b2); zrh = h16(z)
//   out = zrh @ Wro + b_ro
// ---------------------------------------------------------------------------

static constexpr int BATCH = 8192;
static constexpr int DIN   = 1024;
static constexpr int PATHD = 256;
static constexpr int HID   = 1024;
static constexpr int NSTEP = 50;
static constexpr int NGEMM = 2 * NSTEP;          // 100
static constexpr int ROWB  = BATCH / 128;        // 64 row blocks
static constexpr int TPG   = (BATCH / 128) * (HID / 128);  // 512 tiles/GEMM
static constexpr int NTILE = NGEMM * TPG;        // 51200

// ---------------- device scratch ----------------
__device__ __half x0h_buf[(size_t)BATCH * DIN];
__device__ __half gh_buf [(size_t)BATCH * PATHD];
__device__ __half hh_buf [(size_t)BATCH * HID];
__device__ __half zrh_buf[(size_t)BATCH * HID];
__device__ __half qh_buf [(size_t)BATCH * HID];
__device__ float  z_buf  [(size_t)BATCH * HID];
__device__ __half WpeT  [(size_t)PATHD * DIN];
__device__ __half WhiT  [(size_t)HID * DIN];
__device__ __half W1aT  [(size_t)HID * HID];
__device__ __half W1bT  [(size_t)HID * PATHD];
__device__ __half W2T   [(size_t)HID * HID];
__device__ __half WroT  [(size_t)HID * HID];
__device__ float  zero_bias[HID];                // .bss zeros

// sync state (zeroed每 launch)
__device__ unsigned int g_done[NGEMM][ROWB];
__device__ unsigned int g_tile_ctr;

// ---------------- tile configuration ----------------
static constexpr int BM = 128, BN = 128, BK = 32;
static constexpr int STAGES = 4, NTHREADS = 256;
static constexpr int STR  = BK + 8;    // 40 halves = 80B row stride
static constexpr int ASZ  = BM * STR;
static constexpr int BSZ  = BN * STR;
static constexpr int SMEM_BYTES = STAGES * (ASZ + BSZ) * 2; // 81920

__device__ __forceinline__ void ldmx4(uint32_t& r0, uint32_t& r1,
                                      uint32_t& r2, uint32_t& r3, uint32_t a) {
    asm volatile("ldmatrix.sync.aligned.m8n8.x4.shared.b16 {%0,%1,%2,%3}, [%4];"
                 : "=r"(r0), "=r"(r1), "=r"(r2), "=r"(r3) : "r"(a));
}
__device__ __forceinline__ float tanh_ap(float x) {
    float y;
    asm("tanh.approx.f32 %0, %1;" : "=f"(y) : "f"(x));
    return y;
}

// Shared mainloop: acc += A[bm*128 rows, K] @ B[bn*128 rows, K]^T
__device__ __forceinline__ void mainloop_f16(
    const __half* __restrict__ A, const __half* __restrict__ Bw,
    int K, int bm, int bn, __half* As, __half* Bs,
    float (&acc)[4][4][4])
{
    const int tid  = threadIdx.x;
    const int wid  = tid >> 5, lane = tid & 31;
    const int warp_m = wid & 1, warp_n = wid >> 1;   // 2x4 warps: 64x32/warp
    const int KT = K / BK;

#pragma unroll
    for (int a = 0; a < 4; ++a)
#pragma unroll
        for (int b = 0; b < 4; ++b)
#pragma unroll
            for (int c = 0; c < 4; ++c) acc[a][b][c] = 0.f;

    auto load_tile = [&](int kt, int stage) {
        const __half* Ag = A + (size_t)(bm * BM) * K + (size_t)kt * BK;
        __half* Asb = As + stage * ASZ;
#pragma unroll
        for (int i = 0; i < 2; ++i) {
            int lin = i * NTHREADS + tid;
            int r = lin >> 2, c = (lin & 3) << 3;
            uint32_t sa = (uint32_t)__cvta_generic_to_shared(Asb + r * STR + c);
            asm volatile("cp.async.cg.shared.global [%0], [%1], 16;"
                         :: "r"(sa), "l"(Ag + (size_t)r * K + c));
        }
        const __half* Bg = Bw + (size_t)(bn * BN) * K + (size_t)kt * BK;
        __half* Bsb = Bs + stage * BSZ;
#pragma unroll
        for (int i = 0; i < 2; ++i) {
            int lin = i * NTHREADS + tid;
            int r = lin >> 2, c = (lin & 3) << 3;
            uint32_t sa = (uint32_t)__cvta_generic_to_shared(Bsb + r * STR + c);
            asm volatile("cp.async.cg.shared.global [%0], [%1], 16;"
                         :: "r"(sa), "l"(Bg + (size_t)r * K + c));
        }
        asm volatile("cp.async.commit_group;");
    };

    const int a_row  = warp_m * 64 + (lane & 15);
    const int a_koff = (lane >> 4) << 3;
    const int b_row  = warp_n * 32 + (lane & 7) + ((lane >> 4) << 3);
    const int b_koff = ((lane >> 3) & 1) << 3;

    for (int s = 0; s < STAGES - 1 && s < KT; ++s) load_tile(s, s);

    for (int kt = 0; kt < KT; ++kt) {
        if (kt < KT - (STAGES - 1))
            asm volatile("cp.async.wait_group %0;" :: "n"(STAGES - 2));
        else
            asm volatile("cp.async.wait_group 0;");
        __syncthreads();

        int pf = kt + STAGES - 1;
        if (pf < KT) load_tile(pf, pf % STAGES);

        const __half* Asb = As + (kt % STAGES) * ASZ;
        const __half* Bsb = Bs + (kt % STAGES) * BSZ;
        const uint32_t a_base = (uint32_t)__cvta_generic_to_shared(
            Asb + (size_t)a_row * STR + a_koff);
        const uint32_t b_base = (uint32_t)__cvta_generic_to_shared(
            Bsb + (size_t)b_row * STR + b_koff);

#pragma unroll
        for (int ks = 0; ks < BK / 16; ++ks) {
            uint32_t af[4][4], bf[4][2];
#pragma unroll
            for (int mi = 0; mi < 4; ++mi)
                ldmx4(af[mi][0], af[mi][1], af[mi][2], af[mi][3],
                      a_base + (mi * 16 * STR + ks * 16) * 2);
#pragma unroll
            for (int np = 0; np < 2; ++np)
                ldmx4(bf[np*2][0], bf[np*2][1], bf[np*2+1][0], bf[np*2+1][1],
                      b_base + (np * 16 * STR + ks * 16) * 2);
#pragma unroll
            for (int mi = 0; mi < 4; ++mi)
#pragma unroll
                for (int ni = 0; ni < 4; ++ni) {
                    asm volatile(
                        "mma.sync.aligned.m16n8k16.row.col.f32.f16.f16.f32 "
                        "{%0,%1,%2,%3}, {%4,%5,%6,%7}, {%8,%9}, {%0,%1,%2,%3};"
                        : "+f"(acc[mi][ni][0]), "+f"(acc[mi][ni][1]),
                          "+f"(acc[mi][ni][2]), "+f"(acc[mi][ni][3])
                        : "r"(af[mi][0]), "r"(af[mi][1]), "r"(af[mi][2]), "r"(af[mi][3]),
                          "r"(bf[ni][0]), "r"(bf[ni][1]));
                }
        }
        __syncthreads();
    }
}

// ---------------------------------------------------------------------------
// standalone GEMM (prologue / readout)
// MODE 0: Cf = acc + bias
// MODE 3: v = acc + bias; Cf = v; Crh = h16(v)
// MODE 4: Ch = h16(acc + bias)
// ---------------------------------------------------------------------------
template<int MODE>
__global__ __launch_bounds__(NTHREADS, 2)
void gemm_f16(const __half* __restrict__ A, const __half* __restrict__ Bw,
              float* __restrict__ Cf, __half* __restrict__ Ch,
              __half* __restrict__ Crh, int N, int K,
              const float* __restrict__ bias)
{
    extern __shared__ __half smem[];
    __half* As = smem;
    __half* Bs = smem + STAGES * ASZ;
    float acc[4][4][4];
    mainloop_f16(A, Bw, K, blockIdx.y, blockIdx.x, As, Bs, acc);

    const int tid = threadIdx.x, wid = tid >> 5, lane = tid & 31;
    const int gid = lane >> 2, tig = lane & 3;
    const int rbase = blockIdx.y * BM + (wid & 1) * 64;
    const int cbase = blockIdx.x * BN + (wid >> 1) * 32;
#pragma unroll
    for (int mi = 0; mi < 4; ++mi)
#pragma unroll
        for (int h2 = 0; h2 < 2; ++h2) {
            int row = rbase + mi * 16 + h2 * 8 + gid;
#pragma unroll
            for (int ni = 0; ni < 4; ++ni) {
                int col = cbase + ni * 8 + tig * 2;
                float v0 = acc[mi][ni][h2 * 2 + 0] + bias[col];
                float v1 = acc[mi][ni][h2 * 2 + 1] + bias[col + 1];
                size_t off = (size_t)row * N + col;
                if (MODE == 0) {
                    *reinterpret_cast<float2*>(Cf + off) = make_float2(v0, v1);
                } else if (MODE == 3) {
                    *reinterpret_cast<float2*>(Cf + off) = make_float2(v0, v1);
                    *reinterpret_cast<__half2*>(Crh + off) = __floats2half2_rn(v0, v1);
                } else {
                    *reinterpret_cast<__half2*>(Ch + off) = __floats2half2_rn(v0, v1);
                }
            }
        }
}

// ---------------------------------------------------------------------------
// persistent chained-loop kernel (100 GEMMs, tile-level deps)
// ---------------------------------------------------------------------------
__global__ __launch_bounds__(NTHREADS, 2)
void cde_persistent(const __half* __restrict__ W1a, const __half* __restrict__ W2w,
                    __half* __restrict__ zrh, __half* __restrict__ hh,
                    float* __restrict__ z, const __half* __restrict__ qh,
                    const float* __restrict__ b1, const float* __restrict__ b2,
                    float dt)
{
    extern __shared__ __half smem[];
    __half* As = smem;
    __half* Bs = smem + STAGES * ASZ;
    __shared__ unsigned int s_tile;

    const int tid = threadIdx.x, wid = tid >> 5, lane = tid & 31;
    const int gid = lane >> 2, tig = lane & 3;

    while (true) {
        if (tid == 0) s_tile = atomicAdd(&g_tile_ctr, 1u);
        __syncthreads();
        unsigned int tile = s_tile;
        if (tile >= (unsigned)NTILE) break;

        const int gidx = tile >> 9;         // /512
        const int t    = tile & 511;
        const int bm   = t >> 3, bn = t & 7;
        const bool hstep = (gidx & 1) == 0;

        // wait for previous GEMM's row-block bm (8 tiles)
        if (gidx > 0) {
            if (tid == 0) {
                unsigned int* c = &g_done[gidx - 1][bm];
                while (atomicAdd(c, 0u) < 8u) __nanosleep(64);
                __threadfence();
            }
            __syncthreads();
        }

        const __half* A  = hstep ? zrh : hh;
        const __half* Bw = hstep ? W1a : W2w;
        float acc[4][4][4];
        mainloop_f16(A, Bw, HID, bm, bn, As, Bs, acc);

        const int rbase = bm * BM + (wid & 1) * 64;
        const int cbase = bn * BN + (wid >> 1) * 32;
        if (hstep) {
            const float coef = dt * (float)((gidx >> 1) + 1);
#pragma unroll
            for (int mi = 0; mi < 4; ++mi)
#pragma unroll
                for (int h2 = 0; h2 < 2; ++h2) {
                    int row = rbase + mi * 16 + h2 * 8 + gid;
#pragma unroll
                    for (int ni = 0; ni < 4; ++ni) {
                        int col = cbase + ni * 8 + tig * 2;
                        float v0 = acc[mi][ni][h2 * 2 + 0] + b1[col];
                        float v1 = acc[mi][ni][h2 * 2 + 1] + b1[col + 1];
                        size_t off = (size_t)row * HID + col;
                        __half2 qe = __ldcg(reinterpret_cast<const __half2*>(qh + off));
                        float2 e = __half22float2(qe);
                        v0 = tanh_ap(v0 + coef * e.x);
                        v1 = tanh_ap(v1 + coef * e.y);
                        *reinterpret_cast<__half2*>(hh + off) = __floats2half2_rn(v0, v1);
                    }
                }
        } else {
#pragma unroll
            for (int mi = 0; mi < 4; ++mi)
#pragma unroll
                for (int h2 = 0; h2 < 2; ++h2) {
                    int row = rbase + mi * 16 + h2 * 8 + gid;
#pragma unroll
                    for (int ni = 0; ni < 4; ++ni) {
                        int col = cbase + ni * 8 + tig * 2;
                        float v0 = acc[mi][ni][h2 * 2 + 0] + b2[col];
                        float v1 = acc[mi][ni][h2 * 2 + 1] + b2[col + 1];
                        size_t off = (size_t)row * HID + col;
                        float2 e = __ldcg(reinterpret_cast<const float2*>(z + off));
                        v0 = e.x + dt * v0;
                        v1 = e.y + dt * v1;
                        *reinterpret_cast<float2*>(z + off) = make_float2(v0, v1);
                        *reinterpret_cast<__half2*>(zrh + off) = __floats2half2_rn(v0, v1);
                    }
                }
        }

        __threadfence();
        __syncthreads();
        if (tid == 0) atomicAdd(&g_done[gidx][bm], 1u);
    }
}

// ---------------------------------------------------------------------------
// prep kernels
// ---------------------------------------------------------------------------
__global__ void zero_sync()
{
    int i = blockIdx.x * blockDim.x + threadIdx.x;
    unsigned int* p = &g_done[0][0];
    int n = NGEMM * ROWB;
    if (i < n) p[i] = 0;
    if (i == n) g_tile_ctr = 0;
}

__global__ void transpose_h16(const float* __restrict__ in, __half* __restrict__ out,
                              int K, int N)   // [K,N] fp32 -> [N,K] fp16
{
    __shared__ float t[32][33];
    const int k0 = blockIdx.y * 32, n0 = blockIdx.x * 32;
    const int x = threadIdx.x, y = threadIdx.y;
#pragma unroll
    for (int i = 0; i < 32; i += 8)
        t[y + i][x] = in[(size_t)(k0 + y + i) * N + n0 + x];
    __syncthreads();
#pragma unroll
    for (int i = 0; i < 32; i += 8)
        out[(size_t)(n0 + y + i) * K + k0 + x] = __float2half_rn(t[x][y + i]);
}

__global__ void to_h16(const float4* __restrict__ in, __half2* __restrict__ out, int n4)
{
    int i = blockIdx.x * blockDim.x + threadIdx.x;
    if (i < n4) {
        float4 v = in[i];
        out[i * 2 + 0] = __floats2half2_rn(v.x, v.y);
        out[i * 2 + 1] = __floats2half2_rn(v.z, v.w);
    }
}

template<int MODE>
static void run_gemm(const __half* A, const __half* Bw,
                     float* Cf, __half* Ch, __half* Crh,
                     int M, int N, int K, const float* bias)
{
    cudaFuncSetAttribute(gemm_f16<MODE>,
                         cudaFuncAttributeMaxDynamicSharedMemorySize, SMEM_BYTES);
    dim3 grid(N / BN, M / BM);
    gemm_f16<MODE><<<grid, NTHREADS, SMEM_BYTES>>>(A, Bw, Cf, Ch, Crh, N, K, bias);
}

extern "C" void kernel_launch(void* const* d_in, const int* in_sizes, int n_in,
                              void* d_out, int out_size)
{
    const float* x0   = (const float*)d_in[0];
    const float* W_pe = (const float*)d_in[1];
    const float* b_pe = (const float*)d_in[2];
    const float* W_hi = (const float*)d_in[3];
    const float* b_hi = (const float*)d_in[4];
    const float* W1   = (const float*)d_in[5];
    const float* b1   = (const float*)d_in[6];
    const float* W2   = (const float*)d_in[7];
    const float* b2   = (const float*)d_in[8];
    const float* W_ro = (const float*)d_in[9];
    const float* b_ro = (const float*)d_in[10];
    float* out = (float*)d_out;

    __half *x0h, *gh, *hh, *zrh, *qh, *wpe, *whi, *w1a, *w1b, *w2, *wro;
    float *z, *zb;
    cudaGetSymbolAddress((void**)&x0h, x0h_buf);
    cudaGetSymbolAddress((void**)&gh,  gh_buf);
    cudaGetSymbolAddress((void**)&hh,  hh_buf);
    cudaGetSymbolAddress((void**)&zrh, zrh_buf);
    cudaGetSymbolAddress((void**)&qh,  qh_buf);
    cudaGetSymbolAddress((void**)&z,   z_buf);
    cudaGetSymbolAddress((void**)&wpe, WpeT);
    cudaGetSymbolAddress((void**)&whi, WhiT);
    cudaGetSymbolAddress((void**)&w1a, W1aT);
    cudaGetSymbolAddress((void**)&w1b, W1bT);
    cudaGetSymbolAddress((void**)&w2,  W2T);
    cudaGetSymbolAddress((void**)&wro, WroT);
    cudaGetSymbolAddress((void**)&zb,  zero_bias);

    const float dt = 1.0f / (float)NSTEP;
    dim3 tb32(32, 8);

    transpose_h16<<<dim3(PATHD/32, DIN/32), tb32>>>(W_pe, wpe, DIN, PATHD);
    transpose_h16<<<dim3(HID/32,   DIN/32), tb32>>>(W_hi, whi, DIN, HID);
    transpose_h16<<<dim3(HID/32,   HID/32), tb32>>>(W1,   w1a, HID, HID);
    transpose_h16<<<dim3(HID/32,   PATHD/32), tb32>>>(W1 + (size_t)HID * HID, w1b, PATHD, HID);
    transpose_h16<<<dim3(HID/32,   HID/32), tb32>>>(W2,   w2,  HID, HID);
    transpose_h16<<<dim3(HID/32,   HID/32), tb32>>>(W_ro, wro, HID, HID);

    int n4 = (BATCH * DIN) / 4;
    to_h16<<<(n4 + 255) / 256, 256>>>((const float4*)x0, (__half2*)x0h, n4);

    // prologue
    run_gemm<4>(x0h, wpe, nullptr, gh, nullptr, BATCH, PATHD, DIN, b_pe);
    run_gemm<4>(gh,  w1b, nullptr, qh, nullptr, BATCH, HID, PATHD, zb);
    run_gemm<3>(x0h, whi, z, nullptr, zrh,      BATCH, HID, DIN,  b_hi);

    // zero dependency counters, then run the whole 100-GEMM chain persistently
    int nthr = NGEMM * ROWB + 1;
    zero_sync<<<(nthr + 255) / 256, 256>>>();

    int dev = 0, nsm = 148;
    cudaGetDevice(&dev);
    cudaDeviceGetAttribute(&nsm, cudaDevAttrMultiProcessorCount, dev);
    cudaFuncSetAttribute(cde_persistent,
                         cudaFuncAttributeMaxDynamicSharedMemorySize, SMEM_BYTES);
    cde_persistent<<<2 * nsm, NTHREADS, SMEM_BYTES>>>(w1a, w2, zrh, hh, z, qh,
                                                      b1, b2, dt);

    // readout
    run_gemm<0>(zrh, wro, out, nullptr, nullptr, BATCH, HID, HID, b_ro);
}

// round 7
// speedup vs baseline: 3.8852x; 1.4680x over previous
#include <cuda_runtime.h>
#include <cuda_fp16.h>
#include <cstdint>

// ---------------------------------------------------------------------------
// NeuralCDE rollout, algebraically reduced to ONE GEMM per step.
//   y = z @ W1a ;  W21 = W2 @ W1a ;  c = b2 @ W1a
//   u_s = tanh(y_{s-1} + t_s q + b1)
//   y_s = y_{s-1} + dt (u_s @ W21 + c)          <- 49 chained GEMMs (s=1..49)
//   S   = sum_{s=1..50} u_s                     <- elementwise in epilogues
//   z50 = z0 + dt (S @ W2) + b2 ;  out = z50 @ W_ro + b_ro
// fp16 operands, fp32 accumulate, persistent dependency-tracked chain.
// ---------------------------------------------------------------------------

static constexpr int BATCH = 8192;
static constexpr int DIN   = 1024;
static constexpr int PATHD = 256;
static constexpr int HID   = 1024;
static constexpr int NSTEP = 50;
static constexpr int NCHAIN = NSTEP - 1;               // 49 chained GEMMs
static constexpr int ROWB  = BATCH / 128;              // 64
static constexpr int TPG   = ROWB * (HID / 128);       // 512 tiles/GEMM
static constexpr int NTILE = NCHAIN * TPG;             // 25088

// ---------------- device scratch ----------------
__device__ __half x0h_buf[(size_t)BATCH * DIN];
__device__ __half gh_buf [(size_t)BATCH * PATHD];
__device__ __half qh_buf [(size_t)BATCH * HID];
__device__ __half z0h_buf[(size_t)BATCH * HID];
__device__ __half uh_buf [(size_t)BATCH * HID];
__device__ __half Sh_buf [(size_t)BATCH * HID];
__device__ __half zfh_buf[(size_t)BATCH * HID];
__device__ float  z_buf  [(size_t)BATCH * HID];
__device__ float  y_buf  [(size_t)BATCH * HID];
__device__ float  S_buf  [(size_t)BATCH * HID];
__device__ __half WpeT  [(size_t)PATHD * DIN];
__device__ __half WhiT  [(size_t)HID * DIN];
__device__ __half W1aT  [(size_t)HID * HID];
__device__ __half W1bT  [(size_t)HID * PATHD];
__device__ __half W2T   [(size_t)HID * HID];
__device__ __half WroT  [(size_t)HID * HID];
__device__ __half W2h   [(size_t)HID * HID];     // W2 row-major fp16
__device__ __half W21T_b[(size_t)HID * HID];     // (W2@W1a)^T fp16
__device__ float  cvec_b[HID];
__device__ float  zero_bias[HID];

__device__ unsigned int g_done[NCHAIN][ROWB];
__device__ unsigned int g_tile_ctr;

// ---------------- tile configuration ----------------
static constexpr int BM = 128, BN = 128, BK = 32;
static constexpr int STAGES = 4, NTHREADS = 256;
static constexpr int STR  = BK + 8;    // 40 halves = 80B row stride
static constexpr int ASZ  = BM * STR;
static constexpr int BSZ  = BN * STR;
static constexpr int SMEM_BYTES = STAGES * (ASZ + BSZ) * 2; // 81920

__device__ __forceinline__ void ldmx4(uint32_t& r0, uint32_t& r1,
                                      uint32_t& r2, uint32_t& r3, uint32_t a) {
    asm volatile("ldmatrix.sync.aligned.m8n8.x4.shared.b16 {%0,%1,%2,%3}, [%4];"
                 : "=r"(r0), "=r"(r1), "=r"(r2), "=r"(r3) : "r"(a));
}
__device__ __forceinline__ float tanh_ap(float x) {
    float y;
    asm("tanh.approx.f32 %0, %1;" : "=f"(y) : "f"(x));
    return y;
}

// acc = A[bm*128.., :K] @ B[bn*128.., :K]^T
__device__ __forceinline__ void mainloop_f16(
    const __half* __restrict__ A, const __half* __restrict__ Bw,
    int K, int bm, int bn, __half* As, __half* Bs,
    float (&acc)[4][4][4])
{
    const int tid  = threadIdx.x;
    const int wid  = tid >> 5, lane = tid & 31;
    const int warp_m = wid & 1, warp_n = wid >> 1;
    const int KT = K / BK;

#pragma unroll
    for (int a = 0; a < 4; ++a)
#pragma unroll
        for (int b = 0; b < 4; ++b)
#pragma unroll
            for (int c = 0; c < 4; ++c) acc[a][b][c] = 0.f;

    auto load_tile = [&](int kt, int stage) {
        const __half* Ag = A + (size_t)(bm * BM) * K + (size_t)kt * BK;
        __half* Asb = As + stage * ASZ;
#pragma unroll
        for (int i = 0; i < 2; ++i) {
            int lin = i * NTHREADS + tid;
            int r = lin >> 2, c = (lin & 3) << 3;
            uint32_t sa = (uint32_t)__cvta_generic_to_shared(Asb + r * STR + c);
            asm volatile("cp.async.cg.shared.global [%0], [%1], 16;"
                         :: "r"(sa), "l"(Ag + (size_t)r * K + c));
        }
        const __half* Bg = Bw + (size_t)(bn * BN) * K + (size_t)kt * BK;
        __half* Bsb = Bs + stage * BSZ;
#pragma unroll
        for (int i = 0; i < 2; ++i) {
            int lin = i * NTHREADS + tid;
            int r = lin >> 2, c = (lin & 3) << 3;
            uint32_t sa = (uint32_t)__cvta_generic_to_shared(Bsb + r * STR + c);
            asm volatile("cp.async.cg.shared.global [%0], [%1], 16;"
                         :: "r"(sa), "l"(Bg + (size_t)r * K + c));
        }
        asm volatile("cp.async.commit_group;");
    };

    const int a_row  = warp_m * 64 + (lane & 15);
    const int a_koff = (lane >> 4) << 3;
    const int b_row  = warp_n * 32 + (lane & 7) + ((lane >> 4) << 3);
    const int b_koff = ((lane >> 3) & 1) << 3;

    for (int s = 0; s < STAGES - 1 && s < KT; ++s) load_tile(s, s);

    for (int kt = 0; kt < KT; ++kt) {
        if (kt < KT - (STAGES - 1))
            asm volatile("cp.async.wait_group %0;" :: "n"(STAGES - 2));
        else
            asm volatile("cp.async.wait_group 0;");
        __syncthreads();

        int pf = kt + STAGES - 1;
        if (pf < KT) load_tile(pf, pf % STAGES);

        const __half* Asb = As + (kt % STAGES) * ASZ;
        const __half* Bsb = Bs + (kt % STAGES) * BSZ;
        const uint32_t a_base = (uint32_t)__cvta_generic_to_shared(
            Asb + (size_t)a_row * STR + a_koff);
        const uint32_t b_base = (uint32_t)__cvta_generic_to_shared(
            Bsb + (size_t)b_row * STR + b_koff);

#pragma unroll
        for (int ks = 0; ks < BK / 16; ++ks) {
            uint32_t af[4][4], bf[4][2];
#pragma unroll
            for (int mi = 0; mi < 4; ++mi)
                ldmx4(af[mi][0], af[mi][1], af[mi][2], af[mi][3],
                      a_base + (mi * 16 * STR + ks * 16) * 2);
#pragma unroll
            for (int np = 0; np < 2; ++np)
                ldmx4(bf[np*2][0], bf[np*2][1], bf[np*2+1][0], bf[np*2+1][1],
                      b_base + (np * 16 * STR + ks * 16) * 2);
#pragma unroll
            for (int mi = 0; mi < 4; ++mi)
#pragma unroll
                for (int ni = 0; ni < 4; ++ni) {
                    asm volatile(
                        "mma.sync.aligned.m16n8k16.row.col.f32.f16.f16.f32 "
                        "{%0,%1,%2,%3}, {%4,%5,%6,%7}, {%8,%9}, {%0,%1,%2,%3};"
                        : "+f"(acc[mi][ni][0]), "+f"(acc[mi][ni][1]),
                          "+f"(acc[mi][ni][2]), "+f"(acc[mi][ni][3])
                        : "r"(af[mi][0]), "r"(af[mi][1]), "r"(af[mi][2]), "r"(af[mi][3]),
                          "r"(bf[ni][0]), "r"(bf[ni][1]));
                }
        }
        // no trailing sync: the iteration-top barrier orders stage reuse
    }
}

// ---------------------------------------------------------------------------
// standalone GEMM
// MODE 0: Cf = acc + bias
// MODE 3: v = acc + bias; Cf = v; Crh = h16(v)
// MODE 4: Ch = h16(acc + bias)
// MODE 5: v = extraF + coef*acc + bias; Crh = h16(v)
// MODE 6: Cf = acc; u = tanh(acc + coef*extraH + bias); Ch = h16(u); Sf = u
// ---------------------------------------------------------------------------
template<int MODE>
__global__ __launch_bounds__(NTHREADS, 2)
void gemm_f16(const __half* __restrict__ A, const __half* __restrict__ Bw,
              float* __restrict__ Cf, __half* __restrict__ Ch,
              __half* __restrict__ Crh, float* __restrict__ Sf,
              int N, int K,
              const float* __restrict__ bias,
              const float* __restrict__ extraF,
              const __half* __restrict__ extraH,
              float coef)
{
    extern __shared__ __half smem[];
    __half* As = smem;
    __half* Bs = smem + STAGES * ASZ;
    float acc[4][4][4];
    mainloop_f16(A, Bw, K, blockIdx.y, blockIdx.x, As, Bs, acc);

    const int tid = threadIdx.x, wid = tid >> 5, lane = tid & 31;
    const int gid = lane >> 2, tig = lane & 3;
    const int rbase = blockIdx.y * BM + (wid & 1) * 64;
    const int cbase = blockIdx.x * BN + (wid >> 1) * 32;
#pragma unroll
    for (int mi = 0; mi < 4; ++mi)
#pragma unroll
        for (int h2 = 0; h2 < 2; ++h2) {
            int row = rbase + mi * 16 + h2 * 8 + gid;
#pragma unroll
            for (int ni = 0; ni < 4; ++ni) {
                int col = cbase + ni * 8 + tig * 2;
                float a0 = acc[mi][ni][h2 * 2 + 0];
                float a1 = acc[mi][ni][h2 * 2 + 1];
                size_t off = (size_t)row * N + col;
                if (MODE == 0) {
                    *reinterpret_cast<float2*>(Cf + off) =
                        make_float2(a0 + bias[col], a1 + bias[col + 1]);
                } else if (MODE == 3) {
                    float v0 = a0 + bias[col], v1 = a1 + bias[col + 1];
                    *reinterpret_cast<float2*>(Cf + off) = make_float2(v0, v1);
                    *reinterpret_cast<__half2*>(Crh + off) = __floats2half2_rn(v0, v1);
                } else if (MODE == 4) {
                    *reinterpret_cast<__half2*>(Ch + off) =
                        __floats2half2_rn(a0 + bias[col], a1 + bias[col + 1]);
                } else if (MODE == 5) {
                    float2 e = *reinterpret_cast<const float2*>(extraF + off);
                    float v0 = e.x + coef * a0 + bias[col];
                    float v1 = e.y + coef * a1 + bias[col + 1];
                    *reinterpret_cast<__half2*>(Crh + off) = __floats2half2_rn(v0, v1);
                } else { // MODE 6
                    *reinterpret_cast<float2*>(Cf + off) = make_float2(a0, a1);
                    float2 e = __half22float2(
                        *reinterpret_cast<const __half2*>(extraH + off));
                    float u0 = tanh_ap(a0 + coef * e.x + bias[col]);
                    float u1 = tanh_ap(a1 + coef * e.y + bias[col + 1]);
                    *reinterpret_cast<__half2*>(Ch + off) = __floats2half2_rn(u0, u1);
                    *reinterpret_cast<float2*>(Sf + off) = make_float2(u0, u1);
                }
            }
        }
}

// ---------------------------------------------------------------------------
// persistent chain: 49 GEMMs  u_{g+1} @ W21 -> y update -> u_{g+2}, S +=
// ---------------------------------------------------------------------------
__global__ __launch_bounds__(NTHREADS, 2)
void cde_chain(const __half* __restrict__ W21, __half* __restrict__ uh,
               float* __restrict__ y, float* __restrict__ S,
               __half* __restrict__ Sh, const __half* __restrict__ qh,
               const float* __restrict__ b1, const float* __restrict__ cv,
               float dt)
{
    extern __shared__ __half smem[];
    __half* As = smem;
    __half* Bs = smem + STAGES * ASZ;
    __shared__ unsigned int s_tile;

    const int tid = threadIdx.x, wid = tid >> 5, lane = tid & 31;
    const int gid = lane >> 2, tig = lane & 3;

    while (true) {
        if (tid == 0) s_tile = atomicAdd(&g_tile_ctr, 1u);
        __syncthreads();
        unsigned int tile = s_tile;
        if (tile >= (unsigned)NTILE) break;

        const int gidx = tile >> 9;
        const int t    = tile & 511;
        const int bm   = t >> 3, bn = t & 7;

        if (gidx > 0) {
            if (tid == 0) {
                unsigned int* c = &g_done[gidx - 1][bm];
                while (atomicAdd(c, 0u) < 8u) __nanosleep(64);
                __threadfence();
            }
            __syncthreads();
        }

        float acc[4][4][4];
        mainloop_f16(uh, W21, HID, bm, bn, As, Bs, acc);

        const int rbase = bm * BM + (wid & 1) * 64;
        const int cbase = bn * BN + (wid >> 1) * 32;
        const float tcoef = dt * (float)(gidx + 2);
        const bool last = (gidx == NCHAIN - 1);
#pragma unroll
        for (int mi = 0; mi < 4; ++mi)
#pragma unroll
            for (int h2 = 0; h2 < 2; ++h2) {
                int row = rbase + mi * 16 + h2 * 8 + gid;
#pragma unroll
                for (int ni = 0; ni < 4; ++ni) {
                    int col = cbase + ni * 8 + tig * 2;
                    size_t off = (size_t)row * HID + col;
                    float a0 = acc[mi][ni][h2 * 2 + 0] + cv[col];
                    float a1 = acc[mi][ni][h2 * 2 + 1] + cv[col + 1];
                    float2 yv = __ldcg(reinterpret_cast<const float2*>(y + off));
                    float y0 = yv.x + dt * a0;
                    float y1 = yv.y + dt * a1;
                    *reinterpret_cast<float2*>(y + off) = make_float2(y0, y1);

                    float2 qe = __half22float2(
                        *reinterpret_cast<const __half2*>(qh + off));
                    float u0 = tanh_ap(y0 + tcoef * qe.x + b1[col]);
                    float u1 = tanh_ap(y1 + tcoef * qe.y + b1[col + 1]);
                    *reinterpret_cast<__half2*>(uh + off) = __floats2half2_rn(u0, u1);

                    float2 Sv = __ldcg(reinterpret_cast<const float2*>(S + off));
                    Sv.x += u0; Sv.y += u1;
                    *reinterpret_cast<float2*>(S + off) = Sv;
                    if (last)
                        *reinterpret_cast<__half2*>(Sh + off) =
                            __floats2half2_rn(Sv.x, Sv.y);
                }
            }

        __threadfence();
        __syncthreads();
        if (tid == 0) atomicAdd(&g_done[gidx][bm], 1u);
    }
}

// ---------------------------------------------------------------------------
// prep kernels
// ---------------------------------------------------------------------------
__global__ void zero_sync()
{
    int i = blockIdx.x * blockDim.x + threadIdx.x;
    unsigned int* p = &g_done[0][0];
    int n = NCHAIN * ROWB;
    if (i < n) p[i] = 0;
    if (i == n) g_tile_ctr = 0;
}

__global__ void transpose_h16(const float* __restrict__ in, __half* __restrict__ out,
                              int K, int N)
{
    __shared__ float t[32][33];
    const int k0 = blockIdx.y * 32, n0 = blockIdx.x * 32;
    const int x = threadIdx.x, y = threadIdx.y;
#pragma unroll
    for (int i = 0; i < 32; i += 8)
        t[y + i][x] = in[(size_t)(k0 + y + i) * N + n0 + x];
    __syncthreads();
#pragma unroll
    for (int i = 0; i < 32; i += 8)
        out[(size_t)(n0 + y + i) * K + k0 + x] = __float2half_rn(t[x][y + i]);
}

__global__ void to_h16(const float4* __restrict__ in, __half2* __restrict__ out, int n4)
{
    int i = blockIdx.x * blockDim.x + threadIdx.x;
    if (i < n4) {
        float4 v = in[i];
        out[i * 2 + 0] = __floats2half2_rn(v.x, v.y);
        out[i * 2 + 1] = __floats2half2_rn(v.z, v.w);
    }
}

// c[n] = sum_j b2[j] * W1a[j,n]  via w1aT rows (contiguous fp16)
__global__ void compute_c(const __half* __restrict__ w1aT,
                          const float* __restrict__ b2, float* __restrict__ c)
{
    __shared__ float red[256];
    int n = blockIdx.x;
    float s = 0.f;
    for (int j = threadIdx.x; j < HID; j += 256)
        s += b2[j] * __half2float(w1aT[(size_t)n * HID + j]);
    red[threadIdx.x] = s;
    __syncthreads();
    for (int k = 128; k > 0; k >>= 1) {
        if (threadIdx.x < k) red[threadIdx.x] += red[threadIdx.x + k];
        __syncthreads();
    }
    if (threadIdx.x == 0) c[n] = red[0];
}

template<int MODE>
static void run_gemm(const __half* A, const __half* Bw,
                     float* Cf, __half* Ch, __half* Crh, float* Sf,
                     int M, int N, int K, const float* bias,
                     const float* extraF, const __half* extraH, float coef)
{
    cudaFuncSetAttribute(gemm_f16<MODE>,
                         cudaFuncAttributeMaxDynamicSharedMemorySize, SMEM_BYTES);
    dim3 grid(N / BN, M / BM);
    gemm_f16<MODE><<<grid, NTHREADS, SMEM_BYTES>>>(A, Bw, Cf, Ch, Crh, Sf, N, K,
                                                   bias, extraF, extraH, coef);
}

extern "C" void kernel_launch(void* const* d_in, const int* in_sizes, int n_in,
                              void* d_out, int out_size)
{
    const float* x0   = (const float*)d_in[0];
    const float* W_pe = (const float*)d_in[1];
    const float* b_pe = (const float*)d_in[2];
    const float* W_hi = (const float*)d_in[3];
    const float* b_hi = (const float*)d_in[4];
    const float* W1   = (const float*)d_in[5];
    const float* b1   = (const float*)d_in[6];
    const float* W2   = (const float*)d_in[7];
    const float* b2   = (const float*)d_in[8];
    const float* W_ro = (const float*)d_in[9];
    const float* b_ro = (const float*)d_in[10];
    float* out = (float*)d_out;

    __half *x0h, *gh, *qh, *z0h, *uh, *Shp, *zfh;
    __half *wpe, *whi, *w1a, *w1b, *w2t, *wro, *w2h, *w21;
    float *z, *y, *S, *cv, *zb;
    cudaGetSymbolAddress((void**)&x0h, x0h_buf);
    cudaGetSymbolAddress((void**)&gh,  gh_buf);
    cudaGetSymbolAddress((void**)&qh,  qh_buf);
    cudaGetSymbolAddress((void**)&z0h, z0h_buf);
    cudaGetSymbolAddress((void**)&uh,  uh_buf);
    cudaGetSymbolAddress((void**)&Shp, Sh_buf);
    cudaGetSymbolAddress((void**)&zfh, zfh_buf);
    cudaGetSymbolAddress((void**)&z,   z_buf);
    cudaGetSymbolAddress((void**)&y,   y_buf);
    cudaGetSymbolAddress((void**)&S,   S_buf);
    cudaGetSymbolAddress((void**)&wpe, WpeT);
    cudaGetSymbolAddress((void**)&whi, WhiT);
    cudaGetSymbolAddress((void**)&w1a, W1aT);
    cudaGetSymbolAddress((void**)&w1b, W1bT);
    cudaGetSymbolAddress((void**)&w2t, W2T);
    cudaGetSymbolAddress((void**)&wro, WroT);
    cudaGetSymbolAddress((void**)&w2h, W2h);
    cudaGetSymbolAddress((void**)&w21, W21T_b);
    cudaGetSymbolAddress((void**)&cv,  cvec_b);
    cudaGetSymbolAddress((void**)&zb,  zero_bias);

    const float dt = 1.0f / (float)NSTEP;
    dim3 tb32(32, 8);

    transpose_h16<<<dim3(PATHD/32, DIN/32), tb32>>>(W_pe, wpe, DIN, PATHD);
    transpose_h16<<<dim3(HID/32,   DIN/32), tb32>>>(W_hi, whi, DIN, HID);
    transpose_h16<<<dim3(HID/32,   HID/32), tb32>>>(W1,   w1a, HID, HID);
    transpose_h16<<<dim3(HID/32,   PATHD/32), tb32>>>(W1 + (size_t)HID * HID, w1b, PATHD, HID);
    transpose_h16<<<dim3(HID/32,   HID/32), tb32>>>(W2,   w2t, HID, HID);
    transpose_h16<<<dim3(HID/32,   HID/32), tb32>>>(W_ro, wro, HID, HID);

    int n4 = (BATCH * DIN) / 4;
    to_h16<<<(n4 + 255) / 256, 256>>>((const float4*)x0, (__half2*)x0h, n4);
    int w4 = (HID * HID) / 4;
    to_h16<<<(w4 + 255) / 256, 256>>>((const float4*)W2, (__half2*)w2h, w4);

    // W21T[n,j] = sum_m W1a[m,n] * W2[j,m]  (A = w1aT, B = W2 row-major)
    run_gemm<4>(w1a, w2h, nullptr, w21, nullptr, nullptr,
                HID, HID, HID, zb, nullptr, nullptr, 0.f);
    compute_c<<<HID, 256>>>(w1a, b2, cv);

    // prologue
    run_gemm<4>(x0h, wpe, nullptr, gh, nullptr, nullptr,
                BATCH, PATHD, DIN, b_pe, nullptr, nullptr, 0.f);
    run_gemm<4>(gh, w1b, nullptr, qh, nullptr, nullptr,
                BATCH, HID, PATHD, zb, nullptr, nullptr, 0.f);
    run_gemm<3>(x0h, whi, z, nullptr, z0h, nullptr,
                BATCH, HID, DIN, b_hi, nullptr, nullptr, 0.f);
    // y0 = z0 @ W1a ; u1 = tanh(y0 + t1 q + b1) ; S = u1
    run_gemm<6>(z0h, w1a, y, uh, nullptr, S,
                BATCH, HID, HID, b1, nullptr, qh, dt);

    // chained 49 GEMMs
    int nthr = NCHAIN * ROWB + 1;
    zero_sync<<<(nthr + 255) / 256, 256>>>();

    int dev = 0, nsm = 148;
    cudaGetDevice(&dev);
    cudaDeviceGetAttribute(&nsm, cudaDevAttrMultiProcessorCount, dev);
    cudaFuncSetAttribute(cde_chain,
                         cudaFuncAttributeMaxDynamicSharedMemorySize, SMEM_BYTES);
    cde_chain<<<2 * nsm, NTHREADS, SMEM_BYTES>>>(w21, uh, y, S, Shp, qh, b1, cv, dt);

    // z50 = z0 + dt (S @ W2) + b2 ; out = z50 @ W_ro + b_ro
    run_gemm<5>(Shp, w2t, nullptr, nullptr, zfh, nullptr,
                BATCH, HID, HID, b2, z, nullptr, dt);
    run_gemm<0>(zfh, wro, out, nullptr, nullptr, nullptr,
                BATCH, HID, HID, b_ro, nullptr, nullptr, 0.f);
}